// round 1
// baseline (speedup 1.0000x reference)
#include <cuda_runtime.h>

#define BB   256
#define IN   1024
#define OUTN 1024

#define OT 32   // out-cols per block (lane dimension)
#define BT 8    // batch rows per block (warp dimension)
#define IC 64   // i-chunk

// Scratch for effective weights (rules: __device__ global, no allocation)
__device__ float g_Weff[OUTN * IN];

__device__ __forceinline__ float tanh_fast(float x) {
    float y;
    asm("tanh.approx.f32 %0, %1;" : "=f"(y) : "f"(x));
    return y;
}

// ---------------------------------------------------------------------------
// Kernel 1: W_eff[o,i] = sum_k softmax(f_logits[o,i,:])_k * atom_k(W[o,i])
// atoms = [identity, tanh, sin].  1M elements; negligible cost, so use
// precise tanhf/sinf here to keep W_eff error tiny.
// ---------------------------------------------------------------------------
__global__ __launch_bounds__(256) void weff_kernel(
    const float* __restrict__ W,
    const float* __restrict__ fl)
{
    int idx = blockIdx.x * blockDim.x + threadIdx.x;
    if (idx >= OUTN * IN) return;
    float w  = W[idx];
    float l0 = fl[3 * idx + 0];
    float l1 = fl[3 * idx + 1];
    float l2 = fl[3 * idx + 2];
    float m  = fmaxf(l0, fmaxf(l1, l2));
    float e0 = __expf(l0 - m);
    float e1 = __expf(l1 - m);
    float e2 = __expf(l2 - m);
    float inv = 1.0f / (e0 + e1 + e2);
    float t = tanhf(w);
    float s = sinf(w);
    g_Weff[idx] = (e0 * w + e1 * t + e2 * s) * inv;
}

// ---------------------------------------------------------------------------
// Kernel 2: out[b,o] = sum_i tanh(h[b,i] * W_eff[o,i]) + bias[o]
// Block tile: OT=32 outs x BT=8 batches, 256 threads (8 warps).
// warp = batch row (h broadcast from smem), lane = out col (stride-1 smem).
// MUFU-bound: 268M tanh / (148 SM * 16 tanh/cyc) ~ 113K cycles.
// ---------------------------------------------------------------------------
__global__ __launch_bounds__(256, 7) void qfbn_main_kernel(
    const float* __restrict__ h,
    const float* __restrict__ bias,
    float* __restrict__ out)
{
    __shared__ float ws[IC][OT + 1];   // W_eff chunk, transposed [i][o]
    __shared__ float hs[IC][BT + 1];   // h chunk, transposed [i][b]

    const int lane  = threadIdx.x & 31;
    const int warp  = threadIdx.x >> 5;          // 0..7 -> batch row in tile
    const int otile = blockIdx.x * OT;
    const int btile = blockIdx.y * BT;

    float acc0 = 0.f, acc1 = 0.f, acc2 = 0.f, acc3 = 0.f;

    for (int i0 = 0; i0 < IN; i0 += IC) {
        // Load W_eff tile: OT rows x IC cols as float4 (512 slots / 256 thr)
        #pragma unroll
        for (int s = threadIdx.x; s < OT * (IC / 4); s += 256) {
            int o = s >> 4;          // / (IC/4)
            int g = s & 15;
            float4 v = *reinterpret_cast<const float4*>(
                &g_Weff[(otile + o) * IN + i0 + g * 4]);
            ws[g * 4 + 0][o] = v.x;
            ws[g * 4 + 1][o] = v.y;
            ws[g * 4 + 2][o] = v.z;
            ws[g * 4 + 3][o] = v.w;
        }
        // Load h tile: BT rows x IC cols (128 slots)
        if (threadIdx.x < BT * (IC / 4)) {
            int b = threadIdx.x >> 4;
            int g = threadIdx.x & 15;
            float4 v = *reinterpret_cast<const float4*>(
                &h[(btile + b) * IN + i0 + g * 4]);
            hs[g * 4 + 0][b] = v.x;
            hs[g * 4 + 1][b] = v.y;
            hs[g * 4 + 2][b] = v.z;
            hs[g * 4 + 3][b] = v.w;
        }
        __syncthreads();

        #pragma unroll
        for (int i = 0; i < IC; i += 4) {
            float w0 = ws[i + 0][lane];
            float w1 = ws[i + 1][lane];
            float w2 = ws[i + 2][lane];
            float w3 = ws[i + 3][lane];
            float h0 = hs[i + 0][warp];
            float h1 = hs[i + 1][warp];
            float h2 = hs[i + 2][warp];
            float h3 = hs[i + 3][warp];
            acc0 += tanh_fast(h0 * w0);
            acc1 += tanh_fast(h1 * w1);
            acc2 += tanh_fast(h2 * w2);
            acc3 += tanh_fast(h3 * w3);
        }
        __syncthreads();
    }

    int o = otile + lane;
    int b = btile + warp;
    out[b * OUTN + o] = (acc0 + acc1) + (acc2 + acc3) + bias[o];
}

// ---------------------------------------------------------------------------
// Launch: inputs per metadata order: h, W, b, f_logits. Output float (B, OUT).
// Graph-capturable: two plain kernel launches, no sync, no alloc.
// ---------------------------------------------------------------------------
extern "C" void kernel_launch(void* const* d_in, const int* in_sizes, int n_in,
                              void* d_out, int out_size)
{
    const float* h        = (const float*)d_in[0];
    const float* W        = (const float*)d_in[1];
    const float* bias     = (const float*)d_in[2];
    const float* f_logits = (const float*)d_in[3];
    float* out            = (float*)d_out;

    (void)in_sizes; (void)n_in; (void)out_size;

    weff_kernel<<<(OUTN * IN + 255) / 256, 256>>>(W, f_logits);

    dim3 grid(OUTN / OT, BB / BT);   // 32 x 32 = 1024 blocks
    qfbn_main_kernel<<<grid, 256>>>(h, bias, out);
}

// round 2
// speedup vs baseline: 1.1091x; 1.1091x over previous
#include <cuda_runtime.h>

#define BB   256
#define IN   1024
#define OUTN 1024

#define OT 32   // out-cols per block (lane dimension)
#define BT 8    // batch rows per block (4 warps x RB=2)
#define RB 2    // batch rows per thread (register tile)
#define IC 64   // i-chunk

// Scratch for effective weights (__device__ global: no allocation)
__device__ float g_Weff[OUTN * IN];

__device__ __forceinline__ float tanh_fast(float x) {
    float y;
    asm("tanh.approx.f32 %0, %1;" : "=f"(y) : "f"(x));
    return y;
}

// ---------------------------------------------------------------------------
// Kernel 1: W_eff[o,i] = sum_k softmax(f_logits[o,i,:])_k * atom_k(W[o,i])
// atoms = [identity, tanh, sin]. DRAM-bound (~20MB), ~3us. Precise math here.
// ---------------------------------------------------------------------------
__global__ __launch_bounds__(256) void weff_kernel(
    const float* __restrict__ W,
    const float* __restrict__ fl)
{
    int idx = blockIdx.x * blockDim.x + threadIdx.x;
    if (idx >= OUTN * IN) return;
    float w  = W[idx];
    float l0 = fl[3 * idx + 0];
    float l1 = fl[3 * idx + 1];
    float l2 = fl[3 * idx + 2];
    float m  = fmaxf(l0, fmaxf(l1, l2));
    float e0 = __expf(l0 - m);
    float e1 = __expf(l1 - m);
    float e2 = __expf(l2 - m);
    float inv = 1.0f / (e0 + e1 + e2);
    float t = tanhf(w);
    float s = sinf(w);
    g_Weff[idx] = (e0 * w + e1 * t + e2 * s) * inv;
}

// ---------------------------------------------------------------------------
// Kernel 2: out[b,o] = sum_i tanh(h[b,i] * W_eff[o,i]) + bias[o]
// 128 threads (4 warps). lane = out col, warp = pair of batch rows (RB=2).
// Per i: 1 w-LDS + 2 h-broadcast = 3 crossbar phases / 2 tanh -> LDS at 75%
// of MUFU pace; MUFU is the sole bottleneck (floor ~113K cyc).
// 1024 blocks -> 6.9/SM -> 98.8% wave utilization.
// ---------------------------------------------------------------------------
__global__ __launch_bounds__(128, 8) void qfbn_main_kernel(
    const float* __restrict__ h,
    const float* __restrict__ bias,
    float* __restrict__ out)
{
    __shared__ float ws[IC][OT + 1];   // W_eff chunk, transposed [i][o]
    __shared__ float hs[IC][BT + 1];   // h chunk, transposed [i][b]

    const int lane  = threadIdx.x & 31;
    const int warp  = threadIdx.x >> 5;          // 0..3
    const int b0    = warp * RB;                 // this thread's batch rows
    const int otile = blockIdx.x * OT;
    const int btile = blockIdx.y * BT;

    float acc0 = 0.f, acc1 = 0.f;

    for (int i0 = 0; i0 < IN; i0 += IC) {
        // W_eff tile: OT x IC floats = 512 float4 slots over 128 threads
        #pragma unroll
        for (int s = threadIdx.x; s < OT * (IC / 4); s += 128) {
            int o = s >> 4;          // / (IC/4)
            int g = s & 15;
            float4 v = *reinterpret_cast<const float4*>(
                &g_Weff[(otile + o) * IN + i0 + g * 4]);
            ws[g * 4 + 0][o] = v.x;
            ws[g * 4 + 1][o] = v.y;
            ws[g * 4 + 2][o] = v.z;
            ws[g * 4 + 3][o] = v.w;
        }
        // h tile: BT x IC floats = 128 float4 slots over 128 threads
        {
            int b = threadIdx.x >> 4;
            int g = threadIdx.x & 15;
            float4 v = *reinterpret_cast<const float4*>(
                &h[(btile + b) * IN + i0 + g * 4]);
            hs[g * 4 + 0][b] = v.x;
            hs[g * 4 + 1][b] = v.y;
            hs[g * 4 + 2][b] = v.z;
            hs[g * 4 + 3][b] = v.w;
        }
        __syncthreads();

        #pragma unroll
        for (int i = 0; i < IC; i += 4) {
            #pragma unroll
            for (int j = 0; j < 4; j++) {
                float w  = ws[i + j][lane];        // 128B conflict-free
                float ha = hs[i + j][b0];          // broadcast
                float hb = hs[i + j][b0 + 1];      // broadcast
                acc0 += tanh_fast(ha * w);
                acc1 += tanh_fast(hb * w);
            }
        }
        __syncthreads();
    }

    int o  = otile + lane;
    float bv = bias[o];
    out[(btile + b0    ) * OUTN + o] = acc0 + bv;
    out[(btile + b0 + 1) * OUTN + o] = acc1 + bv;
}

// ---------------------------------------------------------------------------
// Inputs (metadata order): h, W, b, f_logits. Output float (B, OUT).
// Graph-capturable: two kernel launches, no sync, no alloc.
// ---------------------------------------------------------------------------
extern "C" void kernel_launch(void* const* d_in, const int* in_sizes, int n_in,
                              void* d_out, int out_size)
{
    const float* h        = (const float*)d_in[0];
    const float* W        = (const float*)d_in[1];
    const float* bias     = (const float*)d_in[2];
    const float* f_logits = (const float*)d_in[3];
    float* out            = (float*)d_out;

    (void)in_sizes; (void)n_in; (void)out_size;

    weff_kernel<<<(OUTN * IN + 255) / 256, 256>>>(W, f_logits);

    dim3 grid(OUTN / OT, BB / BT);   // 32 x 32 = 1024 blocks
    qfbn_main_kernel<<<grid, 128>>>(h, bias, out);
}